// round 2
// baseline (speedup 1.0000x reference)
#include <cuda_runtime.h>

// y[o*48+p, n, m] = sum_i W0[p,i] * t4[o, (n-1)%56, m, i]
// t4[o, n', m, i] = sum_{j,k} xpad[o, j, n', m+k] * W1[j,k,i]   (pad 3 each side of width)
//
// One CTA per (o, output-row n): 2*56 = 112 CTAs (single wave on 148 SMs), 256 threads.

#define NCH 12      // input channels per o
#define WID 56
#define WPAD 62     // 56 + 3 + 3
#define KS 7
#define NI 9        // intermediate channels
#define NP 48       // output channels per o
#define THREADS 256

__global__ __launch_bounds__(THREADS, 1)
void fused_sepconv_kernel(const float* __restrict__ x,
                          const float* __restrict__ W0,
                          const float* __restrict__ W1,
                          float* __restrict__ out) {
    __shared__ float xs[NCH * WPAD];        // 744
    __shared__ float w1s[NCH * KS * NI];    // 756
    __shared__ float w0s[NP * NI];          // 432
    __shared__ float t4s[WID * NI];         // 504, layout [m][i]

    const int b = blockIdx.x;     // 0..111
    const int o = b / WID;        // 0..1
    const int n = b % WID;        // output row
    const int nin = (n + WID - 1) % WID;  // roll(+1): out row n <- t5 row n-1
    const int t = threadIdx.x;

    // Zero the pad columns (3 left + 3 right per channel row): 12*6 = 72 slots
    if (t < NCH * 6) {
        int j = t / 6;
        int c = t % 6;
        int col = (c < 3) ? c : (WPAD - 6 + c);   // 0..2 or 59..61
        xs[j * WPAD + col] = 0.0f;
    }

    // Load the x row (row nin) for all 12 channels
    for (int idx = t; idx < NCH * WID; idx += THREADS) {
        int j = idx / WID;
        int m = idx % WID;
        xs[j * WPAD + 3 + m] = x[((o * NCH + j) * WID + nin) * WID + m];
    }

    // Load weights — FIX: both loads strided (NP*NI = 432 > THREADS)
    for (int idx = t; idx < NCH * KS * NI; idx += THREADS) w1s[idx] = W1[idx];
    for (int idx = t; idx < NP * NI; idx += THREADS)       w0s[idx] = W0[idx];

    __syncthreads();

    // Stage 2: t4[m][i] = sum_{j,k} xs[j][m+k] * w1s[(j*7+k)*9 + i]
    for (int idx = t; idx < WID * NI; idx += THREADS) {
        int i = idx / WID;
        int m = idx % WID;
        float acc = 0.0f;
        #pragma unroll
        for (int j = 0; j < NCH; ++j) {
            #pragma unroll
            for (int k = 0; k < KS; ++k) {
                acc = fmaf(xs[j * WPAD + m + k], w1s[(j * KS + k) * NI + i], acc);
            }
        }
        t4s[m * NI + i] = acc;   // stride-9 store: conflict-free (gcd(9,32)=1)
    }

    __syncthreads();

    // Stage 3: out[o*48+p, n, m] = sum_i t4s[m][i] * w0s[p][i]
    for (int idx = t; idx < NP * WID; idx += THREADS) {
        int p = idx / WID;
        int m = idx % WID;
        const float* t4row = &t4s[m * NI];
        const float* w0row = &w0s[p * NI];
        float acc = 0.0f;
        #pragma unroll
        for (int i = 0; i < NI; ++i) {
            acc = fmaf(t4row[i], w0row[i], acc);
        }
        out[((o * NP + p) * WID + n) * WID + m] = acc;
    }
}

extern "C" void kernel_launch(void* const* d_in, const int* in_sizes, int n_in,
                              void* d_out, int out_size) {
    // Bind inputs by size for robustness: x=75264, W0=432, W1=756
    const float* x  = (const float*)d_in[0];
    const float* W0 = (const float*)d_in[1];
    const float* W1 = (const float*)d_in[2];
    for (int i = 0; i < n_in; ++i) {
        if (in_sizes[i] == 75264) x  = (const float*)d_in[i];
        else if (in_sizes[i] == 432) W0 = (const float*)d_in[i];
        else if (in_sizes[i] == 756) W1 = (const float*)d_in[i];
    }
    float* out = (float*)d_out;                // (1,96,56,56) = 301056

    fused_sepconv_kernel<<<2 * WID, THREADS>>>(x, W0, W1, out);
}

// round 3
// speedup vs baseline: 1.0037x; 1.0037x over previous
#include <cuda_runtime.h>

// y[o*48+p, n, m] = sum_i W0[p,i] * t4[o, (n-1)%56, m, i]
// t4[o, n', m, i] = sum_{j,k} xpad[o, j, n', m+k] * W1[j,k,i]
//
// One CTA per (o, output-row n): 112 CTAs (single wave), 512 threads (16 warps)
// for latency hiding. Stage 3 register-caches the t4 row per thread.

#define NCH 12
#define WID 56
#define WPAD 62     // 56 + 3 + 3
#define KS 7
#define NI 9
#define NP 48
#define THREADS 512
#define PG 8        // p-groups in stage 3 (48 / 6)
#define PPG 6       // p per thread in stage 3

__global__ __launch_bounds__(THREADS, 1)
void fused_sepconv_kernel(const float* __restrict__ x,
                          const float* __restrict__ W0,
                          const float* __restrict__ W1,
                          float* __restrict__ out) {
    __shared__ float xs[NCH * WPAD];        // 744
    __shared__ float w1s[NCH * KS * NI];    // 756
    __shared__ float w0s[NP * NI];          // 432
    __shared__ float t4s[WID * NI];         // 504, layout [m][i], stride 9 (conflict-free)

    const int b = blockIdx.x;             // 0..111
    const int o = b / WID;
    const int n = b % WID;
    const int nin = (n + WID - 1) % WID;  // roll(+1): out row n <- t5 row n-1
    const int t = threadIdx.x;

    // Zero pad columns (3 left + 3 right per channel): 72 slots
    if (t < NCH * 6) {
        int j = t / 6;
        int c = t % 6;
        int col = (c < 3) ? c : (WID + c);   // 0..2 or 59..61
        xs[j * WPAD + col] = 0.0f;
    }

    // Load x row (row nin) for all 12 channels: 672 elements
    for (int idx = t; idx < NCH * WID; idx += THREADS) {
        int j = idx / WID;
        int m = idx % WID;
        xs[j * WPAD + 3 + m] = x[((o * NCH + j) * WID + nin) * WID + m];
    }
    // Weights: 756 + 432
    for (int idx = t; idx < NCH * KS * NI; idx += THREADS) w1s[idx] = W1[idx];
    for (int idx = t; idx < NP * NI; idx += THREADS)       w0s[idx] = W0[idx];

    __syncthreads();

    // Stage 2: t4[m][i] = sum_{j,k} xs[j][m+k] * w1s[(j*7+k)*9 + i]
    // 504 items, one per thread (504 of 512 active).
    if (t < WID * NI) {
        const int i = t / WID;
        const int m = t % WID;
        float acc = 0.0f;
        #pragma unroll
        for (int j = 0; j < NCH; ++j) {
            #pragma unroll
            for (int k = 0; k < KS; ++k) {
                acc = fmaf(xs[j * WPAD + m + k], w1s[(j * KS + k) * NI + i], acc);
            }
        }
        t4s[m * NI + i] = acc;
    }

    __syncthreads();

    // Stage 3: thread fixes m, caches t4 row in regs, computes 6 p values.
    // 448 of 512 threads active; 6 independent FMA chains per thread.
    if (t < PG * WID) {
        const int m  = t % WID;
        const int pg = t / WID;          // 0..7
        float r[NI];
        #pragma unroll
        for (int i = 0; i < NI; ++i) r[i] = t4s[m * NI + i];

        #pragma unroll
        for (int pp = 0; pp < PPG; ++pp) {
            const int p = pg * PPG + pp;
            const float* w0row = &w0s[p * NI];
            float acc = 0.0f;
            #pragma unroll
            for (int i = 0; i < NI; ++i) {
                acc = fmaf(r[i], w0row[i], acc);
            }
            out[((o * NP + p) * WID + n) * WID + m] = acc;
        }
    }
}

extern "C" void kernel_launch(void* const* d_in, const int* in_sizes, int n_in,
                              void* d_out, int out_size) {
    // Bind inputs by size: x=75264, W0=432, W1=756
    const float* x  = (const float*)d_in[0];
    const float* W0 = (const float*)d_in[1];
    const float* W1 = (const float*)d_in[2];
    for (int i = 0; i < n_in; ++i) {
        if (in_sizes[i] == 75264) x  = (const float*)d_in[i];
        else if (in_sizes[i] == 432) W0 = (const float*)d_in[i];
        else if (in_sizes[i] == 756) W1 = (const float*)d_in[i];
    }
    float* out = (float*)d_out;

    fused_sepconv_kernel<<<2 * WID, THREADS>>>(x, W0, W1, out);
}